// round 13
// baseline (speedup 1.0000x reference)
#include <cuda_runtime.h>
#include <math.h>

// Problem constants
#define BATCH 8
#define NNODES 4096
#define DIN0 64
#define DHID 128
#define DOUT0 64
#define CAP 512          // max neighbors per row (mean ~82 at 2% density; P(>512)~0)

#define LOG2E 1.4426950408889634f
#define NEGBIG (-1.0e30f)

// ---------------- static device scratch (no allocations allowed) -------------
// d_h1 aliasing: [0:2M) = y1 (layer1 score vecs) then h2 (layer2 linear out);
//                [2M:4M) = c (layer1 agg out).
__device__ int   d_col[NNODES * CAP + 16];       // pad: pipelined batch overread
__device__ int   d_deg[NNODES];
__device__ float d_h1[BATCH * NNODES * DHID];    // 16 MB, aliased as above
__device__ float d_wt1[DIN0 * DHID];             // W1^T  [k][c]
__device__ float d_wt2[DHID * DOUT0];            // W2^T  [k][c]
__device__ float d_g1[DIN0 * DIN0];              // G = W1^T W1 (64x64)

// ---------------- weight transposes + G = W1^T W1 (fused) --------------------
__global__ void prep_kernel(const float* __restrict__ W1, const float* __restrict__ W2) {
    int i = blockIdx.x * blockDim.x + threadIdx.x;
    if (i < DHID * DIN0) {            // W1: [128][64] -> wt1[k*128 + c]
        int c = i / DIN0, k = i % DIN0;
        d_wt1[k * DHID + c] = W1[i];
    }
    if (i < DOUT0 * DHID) {           // W2: [64][128] -> wt2[k*64 + c]
        int c = i / DHID, k = i % DHID;
        d_wt2[k * DOUT0 + c] = W2[i];
    }
    if (i < DIN0 * DIN0) {            // G[e][d] = sum_h W1[h][d] * W1[h][e]
        int d = i & 63, e = i >> 6;
        float s = 0.0f;
#pragma unroll 4
        for (int h = 0; h < DHID; h++)
            s = fmaf(W1[h * DIN0 + d], W1[h * DIN0 + e], s);
        d_g1[e * DIN0 + d] = s;
    }
}

// ---------------- build CSR from dense binary graph (float4 scan) ------------
__global__ void build_csr_kernel(const float* __restrict__ graph) {
    const unsigned FULL = 0xffffffffu;
    int row  = blockIdx.x * (blockDim.x >> 5) + (threadIdx.x >> 5);
    int lane = threadIdx.x & 31;
    const float4* g = (const float4*)(graph + (size_t)row * NNODES);
    unsigned lt = (1u << lane) - 1u;
    int cnt = 0;
    int* outp = d_col + row * CAP;
#pragma unroll 2
    for (int base = 0; base < NNODES / 4; base += 32) {
        float4 v = g[base + lane];
        int col0 = (base + lane) * 4;
        unsigned b;
        b = __ballot_sync(FULL, v.x != 0.0f);
        if (v.x != 0.0f) { int p = cnt + __popc(b & lt); if (p < CAP) outp[p] = col0; }
        cnt += __popc(b);
        b = __ballot_sync(FULL, v.y != 0.0f);
        if (v.y != 0.0f) { int p = cnt + __popc(b & lt); if (p < CAP) outp[p] = col0 + 1; }
        cnt += __popc(b);
        b = __ballot_sync(FULL, v.z != 0.0f);
        if (v.z != 0.0f) { int p = cnt + __popc(b & lt); if (p < CAP) outp[p] = col0 + 2; }
        cnt += __popc(b);
        b = __ballot_sync(FULL, v.w != 0.0f);
        if (v.w != 0.0f) { int p = cnt + __popc(b & lt); if (p < CAP) outp[p] = col0 + 3; }
        cnt += __popc(b);
    }
    if (lane == 0) d_deg[row] = (cnt < CAP) ? cnt : CAP;
}

// ---------------- y1 = x @ G (RPB=8, blockDim=64) ----------------------------
__global__ void y1_kernel(const float* __restrict__ x) {
    constexpr int RPB = 8;
    __shared__ float xs[RPB * DIN0];
    long base = (long)blockIdx.x * RPB;
    const float4* xg  = (const float4*)(x + base * DIN0);
    float4*       xs4 = (float4*)xs;
    for (int i = threadIdx.x; i < RPB * DIN0 / 4; i += blockDim.x) xs4[i] = xg[i];
    __syncthreads();

    int c = threadIdx.x;   // 0..63
    float acc[RPB];
#pragma unroll
    for (int r = 0; r < RPB; r++) acc[r] = 0.0f;
    for (int k = 0; k < DIN0; k += 4) {
        float w0 = d_g1[(k + 0) * DIN0 + c];
        float w1 = d_g1[(k + 1) * DIN0 + c];
        float w2 = d_g1[(k + 2) * DIN0 + c];
        float w3 = d_g1[(k + 3) * DIN0 + c];
#pragma unroll
        for (int r = 0; r < RPB; r++) {
            float4 xv = *(const float4*)&xs[r * DIN0 + k];
            acc[r] = fmaf(xv.x, w0, fmaf(xv.y, w1, fmaf(xv.z, w2, fmaf(xv.w, w3, acc[r]))));
        }
    }
#pragma unroll
    for (int r = 0; r < RPB; r++) d_h1[(base + r) * DIN0 + c] = acc[r];
}

// ---------------- fused MLP: h2 = relu(c @ W1^T + b1) @ W2^T -----------------
__global__ void mlp_kernel(const float* __restrict__ b1) {
    __shared__ float xs[8 * DIN0];     // staged c rows
    __shared__ float st[8 * DHID];     // t1 rows
    const float* cbase = d_h1 + (size_t)BATCH * NNODES * DIN0;
    long base = (long)blockIdx.x * 8;

    const float4* xg = (const float4*)(cbase + base * DIN0);
    for (int i = threadIdx.x; i < 8 * DIN0 / 4; i += blockDim.x)
        ((float4*)xs)[i] = xg[i];
    __syncthreads();

    // phase A: t1[r][c] = relu(sum_k c[r][k] wt1[k][c] + b1[c])
    int c = threadIdx.x;               // 0..127
    float b = b1[c];
    float acc[8];
#pragma unroll
    for (int r = 0; r < 8; r++) acc[r] = 0.0f;
    for (int k = 0; k < DIN0; k += 4) {
        float w0 = d_wt1[(k + 0) * DHID + c];
        float w1 = d_wt1[(k + 1) * DHID + c];
        float w2 = d_wt1[(k + 2) * DHID + c];
        float w3 = d_wt1[(k + 3) * DHID + c];
#pragma unroll
        for (int r = 0; r < 8; r++) {
            float4 xv = *(const float4*)&xs[r * DIN0 + k];
            acc[r] = fmaf(xv.x, w0, fmaf(xv.y, w1, fmaf(xv.z, w2, fmaf(xv.w, w3, acc[r]))));
        }
    }
#pragma unroll
    for (int r = 0; r < 8; r++) st[r * DHID + c] = fmaxf(acc[r] + b, 0.0f);
    __syncthreads();

    // phase B: h2[r][c2] = sum_k t1[r][k] wt2[k][c2]
    int c2 = c & 63, half = c >> 6;
    float o0 = 0.f, o1 = 0.f, o2 = 0.f, o3 = 0.f;
    int r0 = half * 4;
    for (int k = 0; k < DHID; k += 4) {
        float w0 = d_wt2[(k + 0) * DOUT0 + c2];
        float w1 = d_wt2[(k + 1) * DOUT0 + c2];
        float w2 = d_wt2[(k + 2) * DOUT0 + c2];
        float w3 = d_wt2[(k + 3) * DOUT0 + c2];
        float4 x0 = *(const float4*)&st[(r0 + 0) * DHID + k];
        float4 x1 = *(const float4*)&st[(r0 + 1) * DHID + k];
        float4 x2 = *(const float4*)&st[(r0 + 2) * DHID + k];
        float4 x3 = *(const float4*)&st[(r0 + 3) * DHID + k];
        o0 = fmaf(x0.x, w0, fmaf(x0.y, w1, fmaf(x0.z, w2, fmaf(x0.w, w3, o0))));
        o1 = fmaf(x1.x, w0, fmaf(x1.y, w1, fmaf(x1.z, w2, fmaf(x1.w, w3, o1))));
        o2 = fmaf(x2.x, w0, fmaf(x2.y, w1, fmaf(x2.z, w2, fmaf(x2.w, w3, o2))));
        o3 = fmaf(x3.x, w0, fmaf(x3.y, w1, fmaf(x3.z, w2, fmaf(x3.w, w3, o3))));
    }
    d_h1[(base + r0 + 0) * DOUT0 + c2] = o0;
    d_h1[(base + r0 + 1) * DOUT0 + c2] = o1;
    d_h1[(base + r0 + 2) * DOUT0 + c2] = o2;
    d_h1[(base + r0 + 3) * DOUT0 + c2] = o3;
}

// ---------------- sparse GAT aggregation (D=64): 2x16-lane engines -----------
// Software-pipelined: batch i+8's indices + value rows are loaded before batch
// i's reduction chain, hiding gather latency under the SHFL/MUFU chain.
template <bool HAS_BIAS>
__device__ __forceinline__ void agg_body64(const float* __restrict__ fsrc,
                                           const float* __restrict__ gsrc,
                                           const float* __restrict__ bias,
                                           float* __restrict__ out) {
    const unsigned FULL = 0xffffffffu;
    int warp  = threadIdx.x >> 5;
    int lane  = threadIdx.x & 31;
    int k16   = lane & 15;
    int grp   = lane >> 4;
    int gbase = grp << 4;

    int row = blockIdx.x * 4 + warp;                 // blockDim=128: 4 warps
    int n = row & (NNODES - 1);
    const float* hb = gsrc + ((size_t)(row - n) << 6);
    unsigned loff = (unsigned)k16 << 2;              // 4 dims per lane

    float4 ft = *(const float4*)(fsrc + ((size_t)row << 6) + loff);
    float f0 = ft.x * LOG2E, f1 = ft.y * LOG2E;
    float f2 = ft.z * LOG2E, f3 = ft.w * LOG2E;

    float M = NEGBIG, Z = 0.0f;
    float a0 = 0.f, a1 = 0.f, a2 = 0.f, a3 = 0.f;
    int deg = d_deg[n];
    const int* cols = d_col + n * CAP;

    // subgroup (k16>>2) -> neighbor slot j: 0->0, 1->2, 2->1, 3->3
    int sub  = k16 >> 2;
    int jmap = ((sub & 1) << 1) | (sub >> 1);
    int thr  = deg - (grp << 2) - jmap;              // slot valid iff i < thr

    // ---- pipeline prologue: load batch 0 ----
    float4 g0, g1, g2, g3;
    {
        int4 c4 = *(const int4*)(cols + (grp << 2));  // overread ok (masked)
        g0 = *(const float4*)(hb + (((unsigned)c4.x << 6) + loff));
        g1 = *(const float4*)(hb + (((unsigned)c4.y << 6) + loff));
        g2 = *(const float4*)(hb + (((unsigned)c4.z << 6) + loff));
        g3 = *(const float4*)(hb + (((unsigned)c4.w << 6) + loff));
    }

    for (int i = 0; i < deg; i += 8) {
        // ---- prefetch batch i+8 (indices + values) ----
        bool more = (i + 8) < deg;
        float4 n0, n1, n2, n3;
        if (more) {
            int4 c4 = *(const int4*)(cols + i + 8 + (grp << 2));
            n0 = *(const float4*)(hb + (((unsigned)c4.x << 6) + loff));
            n1 = *(const float4*)(hb + (((unsigned)c4.y << 6) + loff));
            n2 = *(const float4*)(hb + (((unsigned)c4.z << 6) + loff));
            n3 = *(const float4*)(hb + (((unsigned)c4.w << 6) + loff));
        }

        // ---- process batch i (g0..g3) ----
        float p0 = fmaf(f0, g0.x, fmaf(f1, g0.y, fmaf(f2, g0.z, f3 * g0.w)));
        float p1 = fmaf(f0, g1.x, fmaf(f1, g1.y, fmaf(f2, g1.z, f3 * g1.w)));
        float p2 = fmaf(f0, g2.x, fmaf(f1, g2.y, fmaf(f2, g2.z, f3 * g2.w)));
        float p3 = fmaf(f0, g3.x, fmaf(f1, g3.y, fmaf(f2, g3.z, f3 * g3.w)));

        // merged 4-way reduction within the 16-lane group (5 SHFLs)
        float sA = (k16 & 8) ? p1 : p0, tA = (k16 & 8) ? p0 : p1;
        sA += __shfl_xor_sync(FULL, tA, 8);
        float sB = (k16 & 8) ? p3 : p2, tB = (k16 & 8) ? p2 : p3;
        sB += __shfl_xor_sync(FULL, tB, 8);
        float u  = (k16 & 4) ? sB : sA, ut = (k16 & 4) ? sA : sB;
        u += __shfl_xor_sync(FULL, ut, 4);
        u += __shfl_xor_sync(FULL, u, 2);
        u += __shfl_xor_sync(FULL, u, 1);
        // subgroup holds: base0=d0, base4=d2, base8=d1, base12=d3

        u = (i < thr) ? u : -INFINITY;               // mask invalid slots

        // group max (2 SHFLs)
        float bm = fmaxf(u, __shfl_xor_sync(FULL, u, 4));
        bm = fmaxf(bm, __shfl_xor_sync(FULL, bm, 8));

        if (bm > M) {                                // rare after warmup
            float sc = exp2f(M - bm);
            Z *= sc; a0 *= sc; a1 *= sc; a2 *= sc; a3 *= sc;
            M = bm;
        }
        float w = exp2f(u - M);                      // ONE exp2 for 4 scores

        // Z += sum of the group's 4 weights (2 SHFLs)
        float zs = w + __shfl_xor_sync(FULL, w, 4);
        zs += __shfl_xor_sync(FULL, zs, 8);
        Z += zs;

        // broadcast weights to all group lanes (4 SHFLs)
        float w0 = __shfl_sync(FULL, w, gbase + 0);
        float w1 = __shfl_sync(FULL, w, gbase + 8);
        float w2 = __shfl_sync(FULL, w, gbase + 4);
        float w3 = __shfl_sync(FULL, w, gbase + 12);

        a0 = fmaf(w0, g0.x, a0); a1 = fmaf(w0, g0.y, a1);
        a2 = fmaf(w0, g0.z, a2); a3 = fmaf(w0, g0.w, a3);
        a0 = fmaf(w1, g1.x, a0); a1 = fmaf(w1, g1.y, a1);
        a2 = fmaf(w1, g1.z, a2); a3 = fmaf(w1, g1.w, a3);
        a0 = fmaf(w2, g2.x, a0); a1 = fmaf(w2, g2.y, a1);
        a2 = fmaf(w2, g2.z, a2); a3 = fmaf(w2, g2.w, a3);
        a0 = fmaf(w3, g3.x, a0); a1 = fmaf(w3, g3.y, a1);
        a2 = fmaf(w3, g3.z, a2); a3 = fmaf(w3, g3.w, a3);

        g0 = n0; g1 = n1; g2 = n2; g3 = n3;          // rotate pipeline
    }

    // ---- merge the two groups (flash combine) ----
    float Mo   = __shfl_xor_sync(FULL, M, 16);
    float newM = fmaxf(M, Mo);
    float scl  = exp2f(M - newM);                    // empty group: 0
    Z *= scl; a0 *= scl; a1 *= scl; a2 *= scl; a3 *= scl;
    float Zt = Z + __shfl_xor_sync(FULL, Z, 16);
    float b0 = a0 + __shfl_xor_sync(FULL, a0, 16);
    float b1v = a1 + __shfl_xor_sync(FULL, a1, 16);
    float b2 = a2 + __shfl_xor_sync(FULL, a2, 16);
    float b3 = a3 + __shfl_xor_sync(FULL, a3, 16);

    float inv = 1.0f / Zt;                           // Zt >= 1 (max weight = 1)
    float o0 = b0 * inv, o1 = b1v * inv, o2 = b2 * inv, o3 = b3 * inv;
    if (HAS_BIAS) {
        o0 += bias[loff]; o1 += bias[loff + 1];
        o2 += bias[loff + 2]; o3 += bias[loff + 3];
    }
    if (grp == 0)
        *(float4*)(out + ((size_t)row << 6) + loff) = make_float4(o0, o1, o2, o3);
}

__global__ void agg1_kernel(const float* __restrict__ x) {
    // scores via y1 = x G (fsrc = d_h1[0:2M)); values = x; out = c (d_h1[2M:4M))
    agg_body64<false>(d_h1, x, nullptr, d_h1 + (size_t)BATCH * NNODES * DIN0);
}
__global__ void agg2_kernel(const float* __restrict__ b2, float* __restrict__ out) {
    // scores and values both h2 (d_h1[0:2M), written by mlp_kernel)
    agg_body64<true>(d_h1, d_h1, b2, out);
}

// ---------------- launch ------------------------------------------------------
extern "C" void kernel_launch(void* const* d_in, const int* in_sizes, int n_in,
                              void* d_out, int out_size) {
    const float* flow_x = (const float*)d_in[0];   // [B,N,64]
    const float* graph  = (const float*)d_in[1];   // [N,N]
    const float* W1     = (const float*)d_in[2];   // [128,64]
    const float* b1     = (const float*)d_in[3];   // [128]
    const float* W2     = (const float*)d_in[4];   // [64,128]
    const float* b2     = (const float*)d_in[5];   // [64]
    float*       outp   = (float*)d_out;           // [B,N,1,64]

    // 1) weight transposes + G = W1^T W1 (fused)
    prep_kernel<<<(DHID * DIN0 + 255) / 256, 256>>>(W1, W2);
    // 2) build CSR (shared by both layers & all batches)
    build_csr_kernel<<<NNODES / 8, 256>>>(graph);
    // 3) y1 = x @ G  (64-dim score vectors for layer 1)
    y1_kernel<<<BATCH * NNODES / 8, DIN0>>>(flow_x);
    // 4) layer-1 sparse attention in input space: c = softmax(y1.x) @ x
    agg1_kernel<<<(BATCH * NNODES) / 4, 128>>>(flow_x);
    // 5) fused: h2 = relu(c @ W1^T + b1) @ W2^T
    mlp_kernel<<<BATCH * NNODES / 8, 128>>>(b1);
    // 6) layer-2 sparse attention + bias -> final output
    agg2_kernel<<<(BATCH * NNODES) / 4, 128>>>(b2, outp);
}

// round 14
// speedup vs baseline: 1.0114x; 1.0114x over previous
#include <cuda_runtime.h>
#include <math.h>

// Problem constants
#define BATCH 8
#define NNODES 4096
#define DIN0 64
#define DHID 128
#define DOUT0 64
#define CAP 512          // max neighbors per row (mean ~82 at 2% density; P(>512)~0)

#define LOG2E 1.4426950408889634f
#define NEGBIG (-1.0e30f)

// ---------------- static device scratch (no allocations allowed) -------------
// d_h1 aliasing: [0:2M) = y1 (layer1 scores, b-major) then h2T (node-major);
//                [2M:4M) = c (layer1 agg out, b-major).
__device__ int   d_col[NNODES * CAP + 16];       // pad: int2 tail overread
__device__ int   d_deg[NNODES];
__device__ float d_h1[BATCH * NNODES * DHID];    // 16 MB, aliased as above
__device__ float d_xt[BATCH * NNODES * DIN0];    // 8 MB: x transposed [n][b][d]
__device__ float d_wt1[DIN0 * DHID];             // W1^T  [k][c]
__device__ float d_wt2[DHID * DOUT0];            // W2^T  [k][c]
__device__ float d_g1[DIN0 * DIN0];              // G = W1^T W1 (64x64)

// ---------------- weight transposes + G = W1^T W1 (fused) --------------------
__global__ void prep_kernel(const float* __restrict__ W1, const float* __restrict__ W2) {
    int i = blockIdx.x * blockDim.x + threadIdx.x;
    if (i < DHID * DIN0) {            // W1: [128][64] -> wt1[k*128 + c]
        int c = i / DIN0, k = i % DIN0;
        d_wt1[k * DHID + c] = W1[i];
    }
    if (i < DOUT0 * DHID) {           // W2: [64][128] -> wt2[k*64 + c]
        int c = i / DHID, k = i % DHID;
        d_wt2[k * DOUT0 + c] = W2[i];
    }
    if (i < DIN0 * DIN0) {            // G[e][d] = sum_h W1[h][d] * W1[h][e]
        int d = i & 63, e = i >> 6;
        float s = 0.0f;
#pragma unroll 4
        for (int h = 0; h < DHID; h++)
            s = fmaf(W1[h * DIN0 + d], W1[h * DIN0 + e], s);
        d_g1[e * DIN0 + d] = s;
    }
}

// ---------------- x -> xT [n][b][d] ------------------------------------------
__global__ void xt_kernel(const float* __restrict__ x) {
    int i = blockIdx.x * blockDim.x + threadIdx.x;   // over B*N*16 float4s
    int j = i & 15;
    int row = i >> 4;                 // b*4096 + n
    int n = row & (NNODES - 1), b = row >> 12;
    ((float4*)d_xt)[(((n << 3) + b) << 4) + j] = ((const float4*)x)[i];
}

// ---------------- build CSR from dense binary graph (float4 scan) ------------
__global__ void build_csr_kernel(const float* __restrict__ graph) {
    const unsigned FULL = 0xffffffffu;
    int row  = blockIdx.x * (blockDim.x >> 5) + (threadIdx.x >> 5);
    int lane = threadIdx.x & 31;
    const float4* g = (const float4*)(graph + (size_t)row * NNODES);
    unsigned lt = (1u << lane) - 1u;
    int cnt = 0;
    int* outp = d_col + row * CAP;
#pragma unroll 2
    for (int base = 0; base < NNODES / 4; base += 32) {
        float4 v = g[base + lane];
        int col0 = (base + lane) * 4;
        unsigned b;
        b = __ballot_sync(FULL, v.x != 0.0f);
        if (v.x != 0.0f) { int p = cnt + __popc(b & lt); if (p < CAP) outp[p] = col0; }
        cnt += __popc(b);
        b = __ballot_sync(FULL, v.y != 0.0f);
        if (v.y != 0.0f) { int p = cnt + __popc(b & lt); if (p < CAP) outp[p] = col0 + 1; }
        cnt += __popc(b);
        b = __ballot_sync(FULL, v.z != 0.0f);
        if (v.z != 0.0f) { int p = cnt + __popc(b & lt); if (p < CAP) outp[p] = col0 + 2; }
        cnt += __popc(b);
        b = __ballot_sync(FULL, v.w != 0.0f);
        if (v.w != 0.0f) { int p = cnt + __popc(b & lt); if (p < CAP) outp[p] = col0 + 3; }
        cnt += __popc(b);
    }
    if (lane == 0) d_deg[row] = (cnt < CAP) ? cnt : CAP;
}

// ---------------- y1 = x @ G (RPB=8, blockDim=64) ----------------------------
__global__ void y1_kernel(const float* __restrict__ x) {
    constexpr int RPB = 8;
    __shared__ float xs[RPB * DIN0];
    long base = (long)blockIdx.x * RPB;
    const float4* xg  = (const float4*)(x + base * DIN0);
    float4*       xs4 = (float4*)xs;
    for (int i = threadIdx.x; i < RPB * DIN0 / 4; i += blockDim.x) xs4[i] = xg[i];
    __syncthreads();

    int c = threadIdx.x;   // 0..63
    float acc[RPB];
#pragma unroll
    for (int r = 0; r < RPB; r++) acc[r] = 0.0f;
    for (int k = 0; k < DIN0; k += 4) {
        float w0 = d_g1[(k + 0) * DIN0 + c];
        float w1 = d_g1[(k + 1) * DIN0 + c];
        float w2 = d_g1[(k + 2) * DIN0 + c];
        float w3 = d_g1[(k + 3) * DIN0 + c];
#pragma unroll
        for (int r = 0; r < RPB; r++) {
            float4 xv = *(const float4*)&xs[r * DIN0 + k];
            acc[r] = fmaf(xv.x, w0, fmaf(xv.y, w1, fmaf(xv.z, w2, fmaf(xv.w, w3, acc[r]))));
        }
    }
#pragma unroll
    for (int r = 0; r < RPB; r++) d_h1[(base + r) * DIN0 + c] = acc[r];
}

// ---------------- fused MLP: h2T = relu(c @ W1^T + b1) @ W2^T ----------------
// Reads c (b-major), writes h2 in node-major layout [n][b][d].
__global__ void mlp_kernel(const float* __restrict__ b1) {
    __shared__ float xs[8 * DIN0];     // staged c rows
    __shared__ float st[8 * DHID];     // t1 rows
    const float* cbase = d_h1 + (size_t)BATCH * NNODES * DIN0;
    long base = (long)blockIdx.x * 8;

    const float4* xg = (const float4*)(cbase + base * DIN0);
    for (int i = threadIdx.x; i < 8 * DIN0 / 4; i += blockDim.x)
        ((float4*)xs)[i] = xg[i];
    __syncthreads();

    // phase A: t1[r][c] = relu(sum_k c[r][k] wt1[k][c] + b1[c])
    int c = threadIdx.x;               // 0..127
    float b = b1[c];
    float acc[8];
#pragma unroll
    for (int r = 0; r < 8; r++) acc[r] = 0.0f;
    for (int k = 0; k < DIN0; k += 4) {
        float w0 = d_wt1[(k + 0) * DHID + c];
        float w1 = d_wt1[(k + 1) * DHID + c];
        float w2 = d_wt1[(k + 2) * DHID + c];
        float w3 = d_wt1[(k + 3) * DHID + c];
#pragma unroll
        for (int r = 0; r < 8; r++) {
            float4 xv = *(const float4*)&xs[r * DIN0 + k];
            acc[r] = fmaf(xv.x, w0, fmaf(xv.y, w1, fmaf(xv.z, w2, fmaf(xv.w, w3, acc[r]))));
        }
    }
#pragma unroll
    for (int r = 0; r < 8; r++) st[r * DHID + c] = fmaxf(acc[r] + b, 0.0f);
    __syncthreads();

    // phase B: h2[r][c2] = sum_k t1[r][k] wt2[k][c2]; store node-major
    int c2 = c & 63, half = c >> 6;
    float o0 = 0.f, o1 = 0.f, o2 = 0.f, o3 = 0.f;
    int r0 = half * 4;
    for (int k = 0; k < DHID; k += 4) {
        float w0 = d_wt2[(k + 0) * DOUT0 + c2];
        float w1 = d_wt2[(k + 1) * DOUT0 + c2];
        float w2 = d_wt2[(k + 2) * DOUT0 + c2];
        float w3 = d_wt2[(k + 3) * DOUT0 + c2];
        float4 x0 = *(const float4*)&st[(r0 + 0) * DHID + k];
        float4 x1 = *(const float4*)&st[(r0 + 1) * DHID + k];
        float4 x2 = *(const float4*)&st[(r0 + 2) * DHID + k];
        float4 x3 = *(const float4*)&st[(r0 + 3) * DHID + k];
        o0 = fmaf(x0.x, w0, fmaf(x0.y, w1, fmaf(x0.z, w2, fmaf(x0.w, w3, o0))));
        o1 = fmaf(x1.x, w0, fmaf(x1.y, w1, fmaf(x1.z, w2, fmaf(x1.w, w3, o1))));
        o2 = fmaf(x2.x, w0, fmaf(x2.y, w1, fmaf(x2.z, w2, fmaf(x2.w, w3, o2))));
        o3 = fmaf(x3.x, w0, fmaf(x3.y, w1, fmaf(x3.z, w2, fmaf(x3.w, w3, o3))));
    }
#pragma unroll
    for (int q = 0; q < 4; q++) {
        long rr = base + r0 + q;                       // b-major row id
        int nn = (int)(rr & (NNODES - 1)), bb = (int)(rr >> 12);
        float oq = (q == 0) ? o0 : (q == 1) ? o1 : (q == 2) ? o2 : o3;
        d_h1[((((size_t)nn << 3) + bb) << 6) + c2] = oq;
    }
}

// ---------------- batch-fused sparse aggregation (values node-major) ---------
// Warp = (node n, 2 batches). Two 16-lane subgroups each run a COMPLETE online
// softmax for their batch (no final merge). 2 neighbors per iteration; col
// indices shared across batches; one exp2 covers both neighbor weights.
template <bool FSRC_T, bool HAS_BIAS>
__device__ __forceinline__ void agg_bodyT(const float* __restrict__ fsrc,
                                          const float* __restrict__ vsrc,
                                          const float* __restrict__ bias,
                                          float* __restrict__ out) {
    const unsigned FULL = 0xffffffffu;
    int wid = threadIdx.x >> 5, lane = threadIdx.x & 31;
    int gw = blockIdx.x * 8 + wid;        // 16384 warps
    int n = gw >> 2, bg = gw & 3;
    int s = lane >> 4, j = lane & 15;     // subgroup, lane-in-subgroup
    int b = bg * 2 + s;                   // batch
    int slot = (j >> 3) & 1;              // 0: owns dot0, 1: owns dot1

    const float* frow = FSRC_T
        ? fsrc + ((((size_t)n << 3) + b) << 6) + (j << 2)      // node-major
        : fsrc + ((((size_t)b << 12) + n) << 6) + (j << 2);    // b-major
    float4 ft = *(const float4*)frow;
    float f0 = ft.x * LOG2E, f1 = ft.y * LOG2E;
    float f2 = ft.z * LOG2E, f3 = ft.w * LOG2E;

    const float* vb = vsrc + ((unsigned)b << 6) + ((unsigned)j << 2);

    float M = NEGBIG, Z = 0.0f, a0 = 0.f, a1 = 0.f, a2 = 0.f, a3 = 0.f;
    int deg = d_deg[n];
    const int* cols = d_col + n * CAP;

    for (int i = 0; i < deg; i += 2) {
        int2 cc = *(const int2*)(cols + i);   // aligned; +1 overread padded
        float4 g0 = *(const float4*)(vb + ((size_t)(unsigned)cc.x << 9));
        float4 g1 = *(const float4*)(vb + ((size_t)(unsigned)cc.y << 9));

        float pd0 = fmaf(f0, g0.x, fmaf(f1, g0.y, fmaf(f2, g0.z, f3 * g0.w)));
        float pd1 = fmaf(f0, g1.x, fmaf(f1, g1.y, fmaf(f2, g1.z, f3 * g1.w)));

        // merged 2-way reduction over the 16-lane subgroup (4 SHFLs)
        float sel = (j & 8) ? pd0 : pd1;
        float kee = (j & 8) ? pd1 : pd0;
        float u = kee + __shfl_xor_sync(FULL, sel, 8);
        u += __shfl_xor_sync(FULL, u, 4);
        u += __shfl_xor_sync(FULL, u, 2);
        u += __shfl_xor_sync(FULL, u, 1);
        // lanes j<8: dot0, j>=8: dot1 (replicated within each half)

        if (slot && (i + 1 >= deg)) u = -INFINITY;   // mask odd tail

        float uo = __shfl_xor_sync(FULL, u, 8);      // the other dot
        float bm = fmaxf(u, uo);
        if (bm > M) {                                // subgroup-uniform, rare
            float sc = exp2f(M - bm);                // first iter: 0
            Z *= sc; a0 *= sc; a1 *= sc; a2 *= sc; a3 *= sc;
            M = bm;
        }
        float w  = exp2f(u - M);                     // ONE exp2, both weights
        float wo = __shfl_xor_sync(FULL, w, 8);
        Z += w + wo;
        float w0 = (j & 8) ? wo : w;
        float w1 = (j & 8) ? w : wo;
        a0 = fmaf(w0, g0.x, fmaf(w1, g1.x, a0));
        a1 = fmaf(w0, g0.y, fmaf(w1, g1.y, a1));
        a2 = fmaf(w0, g0.z, fmaf(w1, g1.z, a2));
        a3 = fmaf(w0, g0.w, fmaf(w1, g1.w, a3));
    }

    float inv = 1.0f / Z;                            // Z >= 1 (max weight = 1)
    float o0 = a0 * inv, o1 = a1 * inv, o2 = a2 * inv, o3 = a3 * inv;
    if (HAS_BIAS) {
        o0 += bias[(j << 2)];     o1 += bias[(j << 2) + 1];
        o2 += bias[(j << 2) + 2]; o3 += bias[(j << 2) + 3];
    }
    *(float4*)(out + ((((size_t)b << 12) + n) << 6) + (j << 2)) =
        make_float4(o0, o1, o2, o3);
}

__global__ void agg1_kernel() {
    // scores = y1 (b-major, d_h1[0:2M)); values = xT; out = c (b-major)
    agg_bodyT<false, false>(d_h1, d_xt, nullptr,
                            d_h1 + (size_t)BATCH * NNODES * DIN0);
}
__global__ void agg2_kernel(const float* __restrict__ b2, float* __restrict__ out) {
    // scores and values = h2T (node-major, d_h1[0:2M))
    agg_bodyT<true, true>(d_h1, d_h1, b2, out);
}

// ---------------- launch ------------------------------------------------------
extern "C" void kernel_launch(void* const* d_in, const int* in_sizes, int n_in,
                              void* d_out, int out_size) {
    const float* flow_x = (const float*)d_in[0];   // [B,N,64]
    const float* graph  = (const float*)d_in[1];   // [N,N]
    const float* W1     = (const float*)d_in[2];   // [128,64]
    const float* b1     = (const float*)d_in[3];   // [128]
    const float* W2     = (const float*)d_in[4];   // [64,128]
    const float* b2     = (const float*)d_in[5];   // [64]
    float*       outp   = (float*)d_out;           // [B,N,1,64]

    // 1) weight transposes + G = W1^T W1 (fused)
    prep_kernel<<<(DHID * DIN0 + 255) / 256, 256>>>(W1, W2);
    // 2) build CSR (shared by both layers & all batches)
    build_csr_kernel<<<NNODES / 8, 256>>>(graph);
    // 3) xT = transpose(x) to node-major
    xt_kernel<<<BATCH * NNODES * 16 / 256, 256>>>(flow_x);
    // 4) y1 = x @ G  (64-dim score vectors for layer 1)
    y1_kernel<<<BATCH * NNODES / 8, DIN0>>>(flow_x);
    // 5) layer-1 sparse attention, batch-fused: c = softmax(y1.x) @ x
    agg1_kernel<<<(BATCH / 2) * NNODES / 8, 256>>>();
    // 6) fused MLP: h2T = relu(c @ W1^T + b1) @ W2^T (node-major out)
    mlp_kernel<<<BATCH * NNODES / 8, 128>>>(b1);
    // 7) layer-2 sparse attention, batch-fused + bias -> final output
    agg2_kernel<<<(BATCH / 2) * NNODES / 8, 256>>>(b2, outp);
}

// round 15
// speedup vs baseline: 1.0183x; 1.0069x over previous
#include <cuda_runtime.h>
#include <math.h>

// Problem constants
#define BATCH 8
#define NNODES 4096
#define DIN0 64
#define DHID 128
#define DOUT0 64
#define CAP 512          // max neighbors per row (mean ~82 at 2% density; P(>512)~0)

#define LOG2E 1.4426950408889634f
#define NEGBIG (-1.0e30f)

// ---------------- static device scratch (no allocations allowed) -------------
// d_h1 aliasing: [0:2M) = y1 (layer1 score vecs) then h2 (layer2 linear out);
//                [2M:4M) = c (layer1 agg out).
__device__ int   d_col[NNODES * CAP + 16];       // pad: masked batch overread
__device__ int   d_deg[NNODES];
__device__ float d_h1[BATCH * NNODES * DHID];    // 16 MB, aliased as above
__device__ float d_wt1[DIN0 * DHID];             // W1^T  [k][c]
__device__ float d_wt2[DHID * DOUT0];            // W2^T  [k][c]
__device__ float d_g1[DIN0 * DIN0];              // G = W1^T W1 (64x64)

// ---------------- weight transposes + G = W1^T W1 (fused) --------------------
__global__ void prep_kernel(const float* __restrict__ W1, const float* __restrict__ W2) {
    int i = blockIdx.x * blockDim.x + threadIdx.x;
    if (i < DHID * DIN0) {            // W1: [128][64] -> wt1[k*128 + c]
        int c = i / DIN0, k = i % DIN0;
        d_wt1[k * DHID + c] = W1[i];
    }
    if (i < DOUT0 * DHID) {           // W2: [64][128] -> wt2[k*64 + c]
        int c = i / DHID, k = i % DHID;
        d_wt2[k * DOUT0 + c] = W2[i];
    }
    if (i < DIN0 * DIN0) {            // G[e][d] = sum_h W1[h][d] * W1[h][e]
        int d = i & 63, e = i >> 6;
        float s = 0.0f;
#pragma unroll 4
        for (int h = 0; h < DHID; h++)
            s = fmaf(W1[h * DIN0 + d], W1[h * DIN0 + e], s);
        d_g1[e * DIN0 + d] = s;
    }
}

// ---------------- build CSR from dense binary graph (float4 scan) ------------
__global__ void build_csr_kernel(const float* __restrict__ graph) {
    const unsigned FULL = 0xffffffffu;
    int row  = blockIdx.x * (blockDim.x >> 5) + (threadIdx.x >> 5);
    int lane = threadIdx.x & 31;
    const float4* g = (const float4*)(graph + (size_t)row * NNODES);
    unsigned lt = (1u << lane) - 1u;
    int cnt = 0;
    int* outp = d_col + row * CAP;
#pragma unroll 2
    for (int base = 0; base < NNODES / 4; base += 32) {
        float4 v = g[base + lane];
        int col0 = (base + lane) * 4;
        unsigned b;
        b = __ballot_sync(FULL, v.x != 0.0f);
        if (v.x != 0.0f) { int p = cnt + __popc(b & lt); if (p < CAP) outp[p] = col0; }
        cnt += __popc(b);
        b = __ballot_sync(FULL, v.y != 0.0f);
        if (v.y != 0.0f) { int p = cnt + __popc(b & lt); if (p < CAP) outp[p] = col0 + 1; }
        cnt += __popc(b);
        b = __ballot_sync(FULL, v.z != 0.0f);
        if (v.z != 0.0f) { int p = cnt + __popc(b & lt); if (p < CAP) outp[p] = col0 + 2; }
        cnt += __popc(b);
        b = __ballot_sync(FULL, v.w != 0.0f);
        if (v.w != 0.0f) { int p = cnt + __popc(b & lt); if (p < CAP) outp[p] = col0 + 3; }
        cnt += __popc(b);
    }
    if (lane == 0) d_deg[row] = (cnt < CAP) ? cnt : CAP;
}

// ---------------- y1 = x @ G : G staged in smem, 32 rows/block ---------------
__global__ void y1_kernel(const float* __restrict__ x) {
    __shared__ float gs[DIN0 * DIN0];  // 16 KB
    __shared__ float xs[32 * DIN0];    // 8 KB
    int tid = threadIdx.x;
    long base = (long)blockIdx.x * 32;

    const float4* gg = (const float4*)d_g1;
    for (int i = tid; i < DIN0 * DIN0 / 4; i += 256) ((float4*)gs)[i] = gg[i];
    const float4* xg = (const float4*)(x + base * DIN0);
    for (int i = tid; i < 32 * DIN0 / 4; i += 256) ((float4*)xs)[i] = xg[i];
    __syncthreads();

    int c = tid & 63, rg = tid >> 6;   // rg 0..3 -> rows rg*8 .. rg*8+7
    int r0 = rg * 8;
    float acc[8];
#pragma unroll
    for (int r = 0; r < 8; r++) acc[r] = 0.0f;
    for (int k = 0; k < DIN0; k += 4) {
        float w0 = gs[(k + 0) * DIN0 + c];
        float w1 = gs[(k + 1) * DIN0 + c];
        float w2 = gs[(k + 2) * DIN0 + c];
        float w3 = gs[(k + 3) * DIN0 + c];
#pragma unroll
        for (int r = 0; r < 8; r++) {
            float4 xv = *(const float4*)&xs[(r0 + r) * DIN0 + k];
            acc[r] = fmaf(xv.x, w0, fmaf(xv.y, w1, fmaf(xv.z, w2, fmaf(xv.w, w3, acc[r]))));
        }
    }
#pragma unroll
    for (int r = 0; r < 8; r++) d_h1[(base + r0 + r) * DIN0 + c] = acc[r];
}

// ---------------- fused MLP: h2 = relu(c @ W1^T + b1) @ W2^T -----------------
__global__ void mlp_kernel(const float* __restrict__ b1) {
    __shared__ float xs[8 * DIN0];     // staged c rows
    __shared__ float st[8 * DHID];     // t1 rows
    const float* cbase = d_h1 + (size_t)BATCH * NNODES * DIN0;
    long base = (long)blockIdx.x * 8;

    const float4* xg = (const float4*)(cbase + base * DIN0);
    for (int i = threadIdx.x; i < 8 * DIN0 / 4; i += blockDim.x)
        ((float4*)xs)[i] = xg[i];
    __syncthreads();

    // phase A: t1[r][c] = relu(sum_k c[r][k] wt1[k][c] + b1[c])
    int c = threadIdx.x;               // 0..127
    float b = b1[c];
    float acc[8];
#pragma unroll
    for (int r = 0; r < 8; r++) acc[r] = 0.0f;
    for (int k = 0; k < DIN0; k += 4) {
        float w0 = d_wt1[(k + 0) * DHID + c];
        float w1 = d_wt1[(k + 1) * DHID + c];
        float w2 = d_wt1[(k + 2) * DHID + c];
        float w3 = d_wt1[(k + 3) * DHID + c];
#pragma unroll
        for (int r = 0; r < 8; r++) {
            float4 xv = *(const float4*)&xs[r * DIN0 + k];
            acc[r] = fmaf(xv.x, w0, fmaf(xv.y, w1, fmaf(xv.z, w2, fmaf(xv.w, w3, acc[r]))));
        }
    }
#pragma unroll
    for (int r = 0; r < 8; r++) st[r * DHID + c] = fmaxf(acc[r] + b, 0.0f);
    __syncthreads();

    // phase B: h2[r][c2] = sum_k t1[r][k] wt2[k][c2]
    int c2 = c & 63, half = c >> 6;
    float o0 = 0.f, o1 = 0.f, o2 = 0.f, o3 = 0.f;
    int r0 = half * 4;
    for (int k = 0; k < DHID; k += 4) {
        float w0 = d_wt2[(k + 0) * DOUT0 + c2];
        float w1 = d_wt2[(k + 1) * DOUT0 + c2];
        float w2 = d_wt2[(k + 2) * DOUT0 + c2];
        float w3 = d_wt2[(k + 3) * DOUT0 + c2];
        float4 x0 = *(const float4*)&st[(r0 + 0) * DHID + k];
        float4 x1 = *(const float4*)&st[(r0 + 1) * DHID + k];
        float4 x2 = *(const float4*)&st[(r0 + 2) * DHID + k];
        float4 x3 = *(const float4*)&st[(r0 + 3) * DHID + k];
        o0 = fmaf(x0.x, w0, fmaf(x0.y, w1, fmaf(x0.z, w2, fmaf(x0.w, w3, o0))));
        o1 = fmaf(x1.x, w0, fmaf(x1.y, w1, fmaf(x1.z, w2, fmaf(x1.w, w3, o1))));
        o2 = fmaf(x2.x, w0, fmaf(x2.y, w1, fmaf(x2.z, w2, fmaf(x2.w, w3, o2))));
        o3 = fmaf(x3.x, w0, fmaf(x3.y, w1, fmaf(x3.z, w2, fmaf(x3.w, w3, o3))));
    }
    d_h1[(base + r0 + 0) * DOUT0 + c2] = o0;
    d_h1[(base + r0 + 1) * DOUT0 + c2] = o1;
    d_h1[(base + r0 + 2) * DOUT0 + c2] = o2;
    d_h1[(base + r0 + 3) * DOUT0 + c2] = o3;
}

// ---------------- sparse GAT aggregation (D=64): warp-PAIR per (b,n) row -----
// Each warp of a pair runs the R12 2x16-lane engine over alternating 8-chunks
// of the neighbor list (half h takes i = 8h, 8h+16, ...). States merged via
// smem flash-combine. Doubles warp parallelism; halves chain count per warp.
template <bool HAS_BIAS>
__device__ __forceinline__ void agg_body64(const float* __restrict__ fsrc,
                                           const float* __restrict__ gsrc,
                                           const float* __restrict__ bias,
                                           float* __restrict__ out) {
    const unsigned FULL = 0xffffffffu;
    __shared__ float4 s_acc[2][16];
    __shared__ float2 s_mz[2];

    int wid   = threadIdx.x >> 5;                    // 0..3 (blockDim = 128)
    int lane  = threadIdx.x & 31;
    int w     = wid >> 1;                            // row slot in block
    int half  = wid & 1;                             // which half of the list
    int k16   = lane & 15;
    int grp   = lane >> 4;
    int gbase = grp << 4;

    int row = blockIdx.x * 2 + w;                    // grid exact: B*N/2 blocks
    int n = row & (NNODES - 1);
    const float* hb = gsrc + ((size_t)(row - n) << 6);
    unsigned loff = (unsigned)k16 << 2;              // 4 dims per lane

    float4 ft = *(const float4*)(fsrc + ((size_t)row << 6) + loff);
    float f0 = ft.x * LOG2E, f1 = ft.y * LOG2E;
    float f2 = ft.z * LOG2E, f3 = ft.w * LOG2E;

    float M = NEGBIG, Z = 0.0f;
    float a0 = 0.f, a1 = 0.f, a2 = 0.f, a3 = 0.f;
    int deg = d_deg[n];
    const int* cols = d_col + n * CAP;

    // subgroup (k16>>2) -> neighbor slot j: 0->0, 1->2, 2->1, 3->3
    int sub  = k16 >> 2;
    int jmap = ((sub & 1) << 1) | (sub >> 1);
    int thr  = deg - (grp << 2) - jmap;              // slot valid iff i < thr

    for (int i = half * 8; i < deg; i += 16) {
        int4 c4 = *(const int4*)(cols + i + (grp << 2));
        float4 g0 = *(const float4*)(hb + (((unsigned)c4.x << 6) + loff));
        float4 g1 = *(const float4*)(hb + (((unsigned)c4.y << 6) + loff));
        float4 g2 = *(const float4*)(hb + (((unsigned)c4.z << 6) + loff));
        float4 g3 = *(const float4*)(hb + (((unsigned)c4.w << 6) + loff));

        float p0 = fmaf(f0, g0.x, fmaf(f1, g0.y, fmaf(f2, g0.z, f3 * g0.w)));
        float p1 = fmaf(f0, g1.x, fmaf(f1, g1.y, fmaf(f2, g1.z, f3 * g1.w)));
        float p2 = fmaf(f0, g2.x, fmaf(f1, g2.y, fmaf(f2, g2.z, f3 * g2.w)));
        float p3 = fmaf(f0, g3.x, fmaf(f1, g3.y, fmaf(f2, g3.z, f3 * g3.w)));

        // merged 4-way reduction within the 16-lane group (5 SHFLs)
        float sA = (k16 & 8) ? p1 : p0, tA = (k16 & 8) ? p0 : p1;
        sA += __shfl_xor_sync(FULL, tA, 8);
        float sB = (k16 & 8) ? p3 : p2, tB = (k16 & 8) ? p2 : p3;
        sB += __shfl_xor_sync(FULL, tB, 8);
        float u  = (k16 & 4) ? sB : sA, ut = (k16 & 4) ? sA : sB;
        u += __shfl_xor_sync(FULL, ut, 4);
        u += __shfl_xor_sync(FULL, u, 2);
        u += __shfl_xor_sync(FULL, u, 1);
        // subgroup holds: base0=d0, base4=d2, base8=d1, base12=d3

        u = (i < thr) ? u : -INFINITY;               // mask invalid slots

        // group max (2 SHFLs)
        float bm = fmaxf(u, __shfl_xor_sync(FULL, u, 4));
        bm = fmaxf(bm, __shfl_xor_sync(FULL, bm, 8));

        if (bm > M) {                                // rare after warmup
            float sc = exp2f(M - bm);
            Z *= sc; a0 *= sc; a1 *= sc; a2 *= sc; a3 *= sc;
            M = bm;
        }
        float wgt = exp2f(u - M);                    // ONE exp2 for 4 scores

        // Z += sum of the group's 4 weights (2 SHFLs)
        float zs = wgt + __shfl_xor_sync(FULL, wgt, 4);
        zs += __shfl_xor_sync(FULL, zs, 8);
        Z += zs;

        // broadcast weights to all group lanes (4 SHFLs)
        float w0 = __shfl_sync(FULL, wgt, gbase + 0);
        float w1 = __shfl_sync(FULL, wgt, gbase + 8);
        float w2 = __shfl_sync(FULL, wgt, gbase + 4);
        float w3 = __shfl_sync(FULL, wgt, gbase + 12);

        a0 = fmaf(w0, g0.x, a0); a1 = fmaf(w0, g0.y, a1);
        a2 = fmaf(w0, g0.z, a2); a3 = fmaf(w0, g0.w, a3);
        a0 = fmaf(w1, g1.x, a0); a1 = fmaf(w1, g1.y, a1);
        a2 = fmaf(w1, g1.z, a2); a3 = fmaf(w1, g1.w, a3);
        a0 = fmaf(w2, g2.x, a0); a1 = fmaf(w2, g2.y, a1);
        a2 = fmaf(w2, g2.z, a2); a3 = fmaf(w2, g2.w, a3);
        a0 = fmaf(w3, g3.x, a0); a1 = fmaf(w3, g3.y, a1);
        a2 = fmaf(w3, g3.z, a2); a3 = fmaf(w3, g3.w, a3);
    }

    // ---- merge this warp's two 16-lane groups (flash combine) ----
    float Mo   = __shfl_xor_sync(FULL, M, 16);
    float newM = fmaxf(M, Mo);
    float scl  = exp2f(M - newM);                    // empty group: 0
    Z *= scl; a0 *= scl; a1 *= scl; a2 *= scl; a3 *= scl;
    float Zt = Z + __shfl_xor_sync(FULL, Z, 16);
    float b0 = a0 + __shfl_xor_sync(FULL, a0, 16);
    float b1v = a1 + __shfl_xor_sync(FULL, a1, 16);
    float b2 = a2 + __shfl_xor_sync(FULL, a2, 16);
    float b3 = a3 + __shfl_xor_sync(FULL, a3, 16);

    // ---- cross-warp merge: half=1 publishes; half=0 combines & writes ----
    if (half == 1 && grp == 0) {
        s_acc[w][k16] = make_float4(b0, b1v, b2, b3);
        if (k16 == 0) s_mz[w] = make_float2(newM, Zt);
    }
    __syncthreads();
    if (half == 0) {
        float4 po  = s_acc[w][k16];
        float2 mzo = s_mz[w];
        float Mf = fmaxf(newM, mzo.x);
        float ss = exp2f(newM - Mf);                 // own scale
        float so = exp2f(mzo.x - Mf);                // partner scale (0 if empty)
        float Zf = Zt * ss + mzo.y * so;
        float inv = 1.0f / Zf;                       // Zf >= 1 (max weight = 1)
        float o0 = fmaf(b0, ss, po.x * so) * inv;
        float o1 = fmaf(b1v, ss, po.y * so) * inv;
        float o2 = fmaf(b2, ss, po.z * so) * inv;
        float o3 = fmaf(b3, ss, po.w * so) * inv;
        if (HAS_BIAS) {
            o0 += bias[loff]; o1 += bias[loff + 1];
            o2 += bias[loff + 2]; o3 += bias[loff + 3];
        }
        if (grp == 0)
            *(float4*)(out + ((size_t)row << 6) + loff) = make_float4(o0, o1, o2, o3);
    }
}

__global__ void agg1_kernel(const float* __restrict__ x) {
    // scores via y1 = x G (fsrc = d_h1[0:2M)); values = x; out = c (d_h1[2M:4M))
    agg_body64<false>(d_h1, x, nullptr, d_h1 + (size_t)BATCH * NNODES * DIN0);
}
__global__ void agg2_kernel(const float* __restrict__ b2, float* __restrict__ out) {
    // scores and values both h2 (d_h1[0:2M), written by mlp_kernel)
    agg_body64<true>(d_h1, d_h1, b2, out);
}

// ---------------- launch ------------------------------------------------------
extern "C" void kernel_launch(void* const* d_in, const int* in_sizes, int n_in,
                              void* d_out, int out_size) {
    const float* flow_x = (const float*)d_in[0];   // [B,N,64]
    const float* graph  = (const float*)d_in[1];   // [N,N]
    const float* W1     = (const float*)d_in[2];   // [128,64]
    const float* b1     = (const float*)d_in[3];   // [128]
    const float* W2     = (const float*)d_in[4];   // [64,128]
    const float* b2     = (const float*)d_in[5];   // [64]
    float*       outp   = (float*)d_out;           // [B,N,1,64]

    // 1) weight transposes + G = W1^T W1 (fused)
    prep_kernel<<<(DHID * DIN0 + 255) / 256, 256>>>(W1, W2);
    // 2) build CSR (shared by both layers & all batches)
    build_csr_kernel<<<NNODES / 8, 256>>>(graph);
    // 3) y1 = x @ G  (64-dim score vectors for layer 1)
    y1_kernel<<<BATCH * NNODES / 32, 256>>>(flow_x);
    // 4) layer-1 sparse attention in input space: c = softmax(y1.x) @ x
    agg1_kernel<<<(BATCH * NNODES) / 2, 128>>>(flow_x);
    // 5) fused MLP: h2 = relu(c @ W1^T + b1) @ W2^T
    mlp_kernel<<<BATCH * NNODES / 8, 128>>>(b1);
    // 6) layer-2 sparse attention + bias -> final output
    agg2_kernel<<<(BATCH * NNODES) / 2, 128>>>(b2, outp);
}

// round 16
// speedup vs baseline: 1.0892x; 1.0697x over previous
#include <cuda_runtime.h>
#include <math.h>

// Problem constants
#define BATCH 8
#define NNODES 4096
#define DIN0 64
#define DHID 128
#define DOUT0 64
#define CAP 512          // max neighbors per row (mean ~82 at 2% density; P(>512)~0)

#define LOG2E 1.4426950408889634f
#define NEGBIG (-1.0e30f)

// ---------------- static device scratch (no allocations allowed) -------------
// d_h1 aliasing: [0:2M) = y1 (layer1 score vecs) then h2 (layer2 linear out);
//                [2M:4M) = c (layer1 agg out).
__device__ int   d_col[NNODES * CAP + 16];       // pad: masked batch overread
__device__ int   d_deg[NNODES];
__device__ float d_h1[BATCH * NNODES * DHID];    // 16 MB, aliased as above
__device__ float d_wt1[DIN0 * DHID];             // W1^T  [k][c]
__device__ float d_wt2[DHID * DOUT0];            // W2^T  [k][c]
__device__ float d_g1[DIN0 * DIN0];              // G = W1^T W1 (64x64)

// ---------------- fused: build CSR (blocks 0..511) + weight prep (512+) ------
__global__ void csr_prep_kernel(const float* __restrict__ graph,
                                const float* __restrict__ W1,
                                const float* __restrict__ W2) {
    const unsigned FULL = 0xffffffffu;
    int blk = blockIdx.x;
    if (blk < NNODES / 8) {
        // ---- CSR build: warp per row, float4 scan ----
        int row  = blk * 8 + (threadIdx.x >> 5);
        int lane = threadIdx.x & 31;
        const float4* g = (const float4*)(graph + (size_t)row * NNODES);
        unsigned lt = (1u << lane) - 1u;
        int cnt = 0;
        int* outp = d_col + row * CAP;
#pragma unroll 2
        for (int base = 0; base < NNODES / 4; base += 32) {
            float4 v = g[base + lane];
            int col0 = (base + lane) * 4;
            unsigned b;
            b = __ballot_sync(FULL, v.x != 0.0f);
            if (v.x != 0.0f) { int p = cnt + __popc(b & lt); if (p < CAP) outp[p] = col0; }
            cnt += __popc(b);
            b = __ballot_sync(FULL, v.y != 0.0f);
            if (v.y != 0.0f) { int p = cnt + __popc(b & lt); if (p < CAP) outp[p] = col0 + 1; }
            cnt += __popc(b);
            b = __ballot_sync(FULL, v.z != 0.0f);
            if (v.z != 0.0f) { int p = cnt + __popc(b & lt); if (p < CAP) outp[p] = col0 + 2; }
            cnt += __popc(b);
            b = __ballot_sync(FULL, v.w != 0.0f);
            if (v.w != 0.0f) { int p = cnt + __popc(b & lt); if (p < CAP) outp[p] = col0 + 3; }
            cnt += __popc(b);
        }
        if (lane == 0) d_deg[row] = (cnt < CAP) ? cnt : CAP;
    } else {
        // ---- weight prep: transposes + G = W1^T W1 ----
        int i = (blk - NNODES / 8) * 256 + threadIdx.x;
        if (i < DHID * DIN0) {            // W1: [128][64] -> wt1[k*128 + c]
            int c = i / DIN0, k = i % DIN0;
            d_wt1[k * DHID + c] = W1[i];
        }
        if (i < DOUT0 * DHID) {           // W2: [64][128] -> wt2[k*64 + c]
            int c = i / DHID, k = i % DHID;
            d_wt2[k * DOUT0 + c] = W2[i];
        }
        if (i < DIN0 * DIN0) {            // G[e][d] = sum_h W1[h][d] * W1[h][e]
            int d = i & 63, e = i >> 6;
            float s = 0.0f;
#pragma unroll 4
            for (int h = 0; h < DHID; h++)
                s = fmaf(W1[h * DIN0 + d], W1[h * DIN0 + e], s);
            d_g1[e * DIN0 + d] = s;
        }
    }
}

// ---------------- y1 = x @ G : G staged in smem, 32 rows/block ---------------
__global__ void y1_kernel(const float* __restrict__ x) {
    __shared__ float gs[DIN0 * DIN0];  // 16 KB
    __shared__ float xs[32 * DIN0];    // 8 KB
    int tid = threadIdx.x;
    long base = (long)blockIdx.x * 32;

    const float4* gg = (const float4*)d_g1;
    for (int i = tid; i < DIN0 * DIN0 / 4; i += 256) ((float4*)gs)[i] = gg[i];
    const float4* xg = (const float4*)(x + base * DIN0);
    for (int i = tid; i < 32 * DIN0 / 4; i += 256) ((float4*)xs)[i] = xg[i];
    __syncthreads();

    int c = tid & 63, rg = tid >> 6;   // rg 0..3 -> rows rg*8 .. rg*8+7
    int r0 = rg * 8;
    float acc[8];
#pragma unroll
    for (int r = 0; r < 8; r++) acc[r] = 0.0f;
    for (int k = 0; k < DIN0; k += 4) {
        float w0 = gs[(k + 0) * DIN0 + c];
        float w1 = gs[(k + 1) * DIN0 + c];
        float w2 = gs[(k + 2) * DIN0 + c];
        float w3 = gs[(k + 3) * DIN0 + c];
#pragma unroll
        for (int r = 0; r < 8; r++) {
            float4 xv = *(const float4*)&xs[(r0 + r) * DIN0 + k];
            acc[r] = fmaf(xv.x, w0, fmaf(xv.y, w1, fmaf(xv.z, w2, fmaf(xv.w, w3, acc[r]))));
        }
    }
#pragma unroll
    for (int r = 0; r < 8; r++) d_h1[(base + r0 + r) * DIN0 + c] = acc[r];
}

// ---------------- fused MLP: h2 = relu(c @ W1^T + b1) @ W2^T -----------------
__global__ void mlp_kernel(const float* __restrict__ b1) {
    __shared__ float xs[8 * DIN0];     // staged c rows
    __shared__ float st[8 * DHID];     // t1 rows
    const float* cbase = d_h1 + (size_t)BATCH * NNODES * DIN0;
    long base = (long)blockIdx.x * 8;

    const float4* xg = (const float4*)(cbase + base * DIN0);
    for (int i = threadIdx.x; i < 8 * DIN0 / 4; i += blockDim.x)
        ((float4*)xs)[i] = xg[i];
    __syncthreads();

    // phase A: t1[r][c] = relu(sum_k c[r][k] wt1[k][c] + b1[c])
    int c = threadIdx.x;               // 0..127
    float b = b1[c];
    float acc[8];
#pragma unroll
    for (int r = 0; r < 8; r++) acc[r] = 0.0f;
    for (int k = 0; k < DIN0; k += 4) {
        float w0 = d_wt1[(k + 0) * DHID + c];
        float w1 = d_wt1[(k + 1) * DHID + c];
        float w2 = d_wt1[(k + 2) * DHID + c];
        float w3 = d_wt1[(k + 3) * DHID + c];
#pragma unroll
        for (int r = 0; r < 8; r++) {
            float4 xv = *(const float4*)&xs[r * DIN0 + k];
            acc[r] = fmaf(xv.x, w0, fmaf(xv.y, w1, fmaf(xv.z, w2, fmaf(xv.w, w3, acc[r]))));
        }
    }
#pragma unroll
    for (int r = 0; r < 8; r++) st[r * DHID + c] = fmaxf(acc[r] + b, 0.0f);
    __syncthreads();

    // phase B: h2[r][c2] = sum_k t1[r][k] wt2[k][c2]
    int c2 = c & 63, half = c >> 6;
    float o0 = 0.f, o1 = 0.f, o2 = 0.f, o3 = 0.f;
    int r0 = half * 4;
    for (int k = 0; k < DHID; k += 4) {
        float w0 = d_wt2[(k + 0) * DOUT0 + c2];
        float w1 = d_wt2[(k + 1) * DOUT0 + c2];
        float w2 = d_wt2[(k + 2) * DOUT0 + c2];
        float w3 = d_wt2[(k + 3) * DOUT0 + c2];
        float4 x0 = *(const float4*)&st[(r0 + 0) * DHID + k];
        float4 x1 = *(const float4*)&st[(r0 + 1) * DHID + k];
        float4 x2 = *(const float4*)&st[(r0 + 2) * DHID + k];
        float4 x3 = *(const float4*)&st[(r0 + 3) * DHID + k];
        o0 = fmaf(x0.x, w0, fmaf(x0.y, w1, fmaf(x0.z, w2, fmaf(x0.w, w3, o0))));
        o1 = fmaf(x1.x, w0, fmaf(x1.y, w1, fmaf(x1.z, w2, fmaf(x1.w, w3, o1))));
        o2 = fmaf(x2.x, w0, fmaf(x2.y, w1, fmaf(x2.z, w2, fmaf(x2.w, w3, o2))));
        o3 = fmaf(x3.x, w0, fmaf(x3.y, w1, fmaf(x3.z, w2, fmaf(x3.w, w3, o3))));
    }
    d_h1[(base + r0 + 0) * DOUT0 + c2] = o0;
    d_h1[(base + r0 + 1) * DOUT0 + c2] = o1;
    d_h1[(base + r0 + 2) * DOUT0 + c2] = o2;
    d_h1[(base + r0 + 3) * DOUT0 + c2] = o3;
}

// ---------------- sparse GAT aggregation (D=64): 2x16-lane engines (R12) -----
// Each 16-lane group: online softmax over 4 neighbors/iter (8/warp). Merged
// in-group reduction leaves each score replicated on a 4-lane subgroup -> ONE
// exp2 covers 4 scores. States merged at the end (flash combine). M starts at
// NEGBIG so empty groups give zero weight (not NaN).
template <bool HAS_BIAS>
__device__ __forceinline__ void agg_body64(const float* __restrict__ fsrc,
                                           const float* __restrict__ gsrc,
                                           const float* __restrict__ bias,
                                           float* __restrict__ out) {
    const unsigned FULL = 0xffffffffu;
    int warp  = threadIdx.x >> 5;
    int lane  = threadIdx.x & 31;
    int k16   = lane & 15;
    int grp   = lane >> 4;
    int gbase = grp << 4;

    int row = blockIdx.x * 8 + warp;                 // grid exact: B*N/8 blocks
    int n = row & (NNODES - 1);
    const float* hb = gsrc + ((size_t)(row - n) << 6);
    unsigned loff = (unsigned)k16 << 2;              // 4 dims per lane

    float4 ft = *(const float4*)(fsrc + ((size_t)row << 6) + loff);
    float f0 = ft.x * LOG2E, f1 = ft.y * LOG2E;
    float f2 = ft.z * LOG2E, f3 = ft.w * LOG2E;

    float M = NEGBIG, Z = 0.0f;
    float a0 = 0.f, a1 = 0.f, a2 = 0.f, a3 = 0.f;
    int deg = d_deg[n];
    const int* cols = d_col + n * CAP;

    // subgroup (k16>>2) -> neighbor slot j: 0->0, 1->2, 2->1, 3->3
    int sub  = k16 >> 2;
    int jmap = ((sub & 1) << 1) | (sub >> 1);
    int thr  = deg - (grp << 2) - jmap;              // slot valid iff i < thr

    for (int i = 0; i < deg; i += 8) {
        int4 c4 = *(const int4*)(cols + i + (grp << 2));
        float4 g0 = *(const float4*)(hb + (((unsigned)c4.x << 6) + loff));
        float4 g1 = *(const float4*)(hb + (((unsigned)c4.y << 6) + loff));
        float4 g2 = *(const float4*)(hb + (((unsigned)c4.z << 6) + loff));
        float4 g3 = *(const float4*)(hb + (((unsigned)c4.w << 6) + loff));

        float p0 = fmaf(f0, g0.x, fmaf(f1, g0.y, fmaf(f2, g0.z, f3 * g0.w)));
        float p1 = fmaf(f0, g1.x, fmaf(f1, g1.y, fmaf(f2, g1.z, f3 * g1.w)));
        float p2 = fmaf(f0, g2.x, fmaf(f1, g2.y, fmaf(f2, g2.z, f3 * g2.w)));
        float p3 = fmaf(f0, g3.x, fmaf(f1, g3.y, fmaf(f2, g3.z, f3 * g3.w)));

        // merged 4-way reduction within the 16-lane group (5 SHFLs)
        float sA = (k16 & 8) ? p1 : p0, tA = (k16 & 8) ? p0 : p1;
        sA += __shfl_xor_sync(FULL, tA, 8);
        float sB = (k16 & 8) ? p3 : p2, tB = (k16 & 8) ? p2 : p3;
        sB += __shfl_xor_sync(FULL, tB, 8);
        float u  = (k16 & 4) ? sB : sA, ut = (k16 & 4) ? sA : sB;
        u += __shfl_xor_sync(FULL, ut, 4);
        u += __shfl_xor_sync(FULL, u, 2);
        u += __shfl_xor_sync(FULL, u, 1);
        // subgroup holds: base0=d0, base4=d2, base8=d1, base12=d3

        u = (i < thr) ? u : -INFINITY;               // mask invalid slots

        // group max (2 SHFLs)
        float bm = fmaxf(u, __shfl_xor_sync(FULL, u, 4));
        bm = fmaxf(bm, __shfl_xor_sync(FULL, bm, 8));

        if (bm > M) {                                // rare after warmup
            float sc = exp2f(M - bm);
            Z *= sc; a0 *= sc; a1 *= sc; a2 *= sc; a3 *= sc;
            M = bm;
        }
        float w = exp2f(u - M);                      // ONE exp2 for 4 scores

        // Z += sum of the group's 4 weights (2 SHFLs)
        float zs = w + __shfl_xor_sync(FULL, w, 4);
        zs += __shfl_xor_sync(FULL, zs, 8);
        Z += zs;

        // broadcast weights to all group lanes (4 SHFLs)
        float w0 = __shfl_sync(FULL, w, gbase + 0);
        float w1 = __shfl_sync(FULL, w, gbase + 8);
        float w2 = __shfl_sync(FULL, w, gbase + 4);
        float w3 = __shfl_sync(FULL, w, gbase + 12);

        a0 = fmaf(w0, g0.x, a0); a1 = fmaf(w0, g0.y, a1);
        a2 = fmaf(w0, g0.z, a2); a3 = fmaf(w0, g0.w, a3);
        a0 = fmaf(w1, g1.x, a0); a1 = fmaf(w1, g1.y, a1);
        a2 = fmaf(w1, g1.z, a2); a3 = fmaf(w1, g1.w, a3);
        a0 = fmaf(w2, g2.x, a0); a1 = fmaf(w2, g2.y, a1);
        a2 = fmaf(w2, g2.z, a2); a3 = fmaf(w2, g2.w, a3);
        a0 = fmaf(w3, g3.x, a0); a1 = fmaf(w3, g3.y, a1);
        a2 = fmaf(w3, g3.z, a2); a3 = fmaf(w3, g3.w, a3);
    }

    // ---- merge the two groups (flash combine) ----
    float Mo   = __shfl_xor_sync(FULL, M, 16);
    float newM = fmaxf(M, Mo);
    float scl  = exp2f(M - newM);                    // empty group: 0
    Z *= scl; a0 *= scl; a1 *= scl; a2 *= scl; a3 *= scl;
    float Zt = Z + __shfl_xor_sync(FULL, Z, 16);
    float b0 = a0 + __shfl_xor_sync(FULL, a0, 16);
    float b1v = a1 + __shfl_xor_sync(FULL, a1, 16);
    float b2 = a2 + __shfl_xor_sync(FULL, a2, 16);
    float b3 = a3 + __shfl_xor_sync(FULL, a3, 16);

    float inv = 1.0f / Zt;                           // Zt >= 1 (max weight = 1)
    float o0 = b0 * inv, o1 = b1v * inv, o2 = b2 * inv, o3 = b3 * inv;
    if (HAS_BIAS) {
        o0 += bias[loff]; o1 += bias[loff + 1];
        o2 += bias[loff + 2]; o3 += bias[loff + 3];
    }
    if (grp == 0)
        *(float4*)(out + ((size_t)row << 6) + loff) = make_float4(o0, o1, o2, o3);
}

__global__ void agg1_kernel(const float* __restrict__ x) {
    // scores via y1 = x G (fsrc = d_h1[0:2M)); values = x; out = c (d_h1[2M:4M))
    agg_body64<false>(d_h1, x, nullptr, d_h1 + (size_t)BATCH * NNODES * DIN0);
}
__global__ void agg2_kernel(const float* __restrict__ b2, float* __restrict__ out) {
    // scores and values both h2 (d_h1[0:2M), written by mlp_kernel)
    agg_body64<true>(d_h1, d_h1, b2, out);
}

// ---------------- launch ------------------------------------------------------
extern "C" void kernel_launch(void* const* d_in, const int* in_sizes, int n_in,
                              void* d_out, int out_size) {
    const float* flow_x = (const float*)d_in[0];   // [B,N,64]
    const float* graph  = (const float*)d_in[1];   // [N,N]
    const float* W1     = (const float*)d_in[2];   // [128,64]
    const float* b1     = (const float*)d_in[3];   // [128]
    const float* W2     = (const float*)d_in[4];   // [64,128]
    const float* b2     = (const float*)d_in[5];   // [64]
    float*       outp   = (float*)d_out;           // [B,N,1,64]

    // 1) CSR build (blocks 0..511) + weight prep / G (blocks 512..543), fused
    csr_prep_kernel<<<NNODES / 8 + 32, 256>>>(graph, W1, W2);
    // 2) y1 = x @ G  (64-dim score vectors for layer 1)
    y1_kernel<<<BATCH * NNODES / 32, 256>>>(flow_x);
    // 3) layer-1 sparse attention in input space: c = softmax(y1.x) @ x
    agg1_kernel<<<(BATCH * NNODES) / 8, 256>>>(flow_x);
    // 4) fused MLP: h2 = relu(c @ W1^T + b1) @ W2^T
    mlp_kernel<<<BATCH * NNODES / 8, 128>>>(b1);
    // 5) layer-2 sparse attention + bias -> final output
    agg2_kernel<<<(BATCH * NNODES) / 8, 256>>>(b2, outp);
}